// round 5
// baseline (speedup 1.0000x reference)
#include <cuda_runtime.h>
#include <cuda_bf16.h>

// CALayer SE, single-pass persistent kernel with L2 retention.
// 512 co-resident blocks, 8 rounds (2 batches each). Phase A: read chunk with
// ld.ca (fills L2), sum, publish. Prefetch next round's chunk to L2, then
// barrier. MLP for 2 batches. Phase C: re-read chunk (L2 hit), scale, st.cs.
// DRAM traffic = read x once + write out once = 537MB.

#define BATCH 16
#define CHAN 256
#define CR 16
#define HW 16384               // floats per plane
#define PLANE_F4 (HW/4)        // 4096
#define HALF_F4 (HW/8)         // 2048
#define NBLK 512
#define TPB 256
#define BPR 2                  // batches per round
#define NROUNDS (BATCH/BPR)    // 8

__device__ float g_part[BATCH * CHAN * 2];
__device__ int   g_cnt[NROUNDS];

__global__ void init_kernel() {
    if (threadIdx.x < NROUNDS) g_cnt[threadIdx.x] = 0;
}

__device__ __forceinline__ void stcs4(float4* p, float4 v) {
    asm volatile("st.global.cs.v4.f32 [%0], {%1,%2,%3,%4};"
                 :: "l"(p), "f"(v.x), "f"(v.y), "f"(v.z), "f"(v.w) : "memory");
}
__device__ __forceinline__ void prefetchL2(const void* p) {
    asm volatile("prefetch.global.L2 [%0];" :: "l"(p));
}

__global__ __launch_bounds__(TPB, 4) void fused_se_kernel(
    const float* __restrict__ x, float* __restrict__ out,
    const float* __restrict__ w1, const float* __restrict__ b1,
    const float* __restrict__ w2, const float* __restrict__ b2)
{
    __shared__ float sred[BPR][8];
    __shared__ float smean[BPR][CHAN];
    __shared__ float shid[BPR][CR];
    __shared__ float sscale[BPR];

    const int chan = blockIdx.x >> 1;          // 0..255
    const int half = blockIdx.x & 1;
    const int tid  = threadIdx.x;
    const int lane = tid & 31;
    const int wid  = tid >> 5;
    const size_t chunk_off = (size_t)half * HALF_F4;   // within plane, in f4

    const float4* __restrict__ x4 = reinterpret_cast<const float4*>(x);
    float4* __restrict__ o4 = reinterpret_cast<float4*>(out);

    for (int round = 0; round < NROUNDS; round++) {
        const int b0 = round * BPR;

        // ---- Phase A: read (ld.ca -> L2 resident), sum, publish ----
        #pragma unroll
        for (int s = 0; s < BPR; s++) {
            const int p = ((b0 + s) << 8) | chan;
            const float4* __restrict__ xp = x4 + (size_t)p * PLANE_F4 + chunk_off;
            float acc = 0.f;
            #pragma unroll
            for (int i = 0; i < 8; i++) {
                float4 v = xp[tid + i * TPB];   // default .ca
                acc += (v.x + v.y) + (v.z + v.w);
            }
            #pragma unroll
            for (int o = 16; o; o >>= 1) acc += __shfl_xor_sync(0xFFFFFFFF, acc, o);
            if (lane == 0) sred[s][wid] = acc;
        }
        __syncthreads();
        if (tid == 0) {
            #pragma unroll
            for (int s = 0; s < BPR; s++) {
                float t = 0.f;
                #pragma unroll
                for (int w = 0; w < 8; w++) t += sred[s][w];
                const int p = ((b0 + s) << 8) | chan;
                g_part[p * 2 + half] = t;
            }
            __threadfence();
            atomicAdd(&g_cnt[round], 1);
        }

        // ---- Prefetch next round's chunk into L2 (hides barrier+MLP) ----
        if (round + 1 < NROUNDS) {
            #pragma unroll
            for (int s = 0; s < BPR; s++) {
                const int p = ((b0 + BPR + s) << 8) | chan;
                const char* base = reinterpret_cast<const char*>(
                    x4 + (size_t)p * PLANE_F4 + chunk_off);
                // 32KB chunk = 256 lines of 128B; 256 threads -> 1 line each
                prefetchL2(base + tid * 128);
            }
        }

        // ---- Barrier: all 512 blocks published this round ----
        if (tid == 0) {
            while (atomicAdd(&g_cnt[round], 0) < NBLK) __nanosleep(64);
            __threadfence();
        }
        __syncthreads();

        // ---- Means for BPR batches ----
        #pragma unroll
        for (int s = 0; s < BPR; s++) {
            const int q = (((b0 + s) << 8) + tid) * 2;
            smean[s][tid] = (__ldcg(&g_part[q]) + __ldcg(&g_part[q + 1])) * (1.0f / HW);
        }
        __syncthreads();

        // ---- Hidden layer: 32 rows (2 batches x 16) over 8 warps ----
        #pragma unroll
        for (int j = 0; j < 4; j++) {
            const int row = wid * 4 + j;
            const int s = row >> 4;
            const int r = row & 15;
            float acc = 0.f;
            #pragma unroll
            for (int c = lane; c < CHAN; c += 32)
                acc += __ldg(&w1[r * CHAN + c]) * smean[s][c];
            #pragma unroll
            for (int o = 16; o; o >>= 1) acc += __shfl_xor_sync(0xFFFFFFFF, acc, o);
            if (lane == 0) shid[s][r] = fmaxf(acc + __ldg(&b1[r]), 0.f);
        }
        __syncthreads();

        // ---- Gates for this block's channel ----
        if (tid < BPR) {
            float acc = __ldg(&b2[chan]);
            #pragma unroll
            for (int r = 0; r < CR; r++)
                acc += __ldg(&w2[chan * CR + r]) * shid[tid][r];
            sscale[tid] = 1.0f / (1.0f + __expf(-acc));
        }
        __syncthreads();

        // ---- Phase C: re-read from L2, scale, stream out ----
        #pragma unroll
        for (int s = 0; s < BPR; s++) {
            const int p = ((b0 + s) << 8) | chan;
            const float sc = sscale[s];
            const float4* __restrict__ xp = x4 + (size_t)p * PLANE_F4 + chunk_off;
            float4* __restrict__ op = o4 + (size_t)p * PLANE_F4 + chunk_off;
            #pragma unroll
            for (int i = 0; i < 8; i++) {
                float4 v = xp[tid + i * TPB];   // L2 hit
                v.x *= sc; v.y *= sc; v.z *= sc; v.w *= sc;
                stcs4(&op[tid + i * TPB], v);
            }
        }
        __syncthreads();
    }
}

extern "C" void kernel_launch(void* const* d_in, const int* in_sizes, int n_in,
                              void* d_out, int out_size) {
    const float* x  = (const float*)d_in[0];
    const float* w1 = (const float*)d_in[1];
    const float* b1 = (const float*)d_in[2];
    const float* w2 = (const float*)d_in[3];
    const float* b2 = (const float*)d_in[4];
    float* out = (float*)d_out;

    init_kernel<<<1, 32>>>();
    fused_se_kernel<<<NBLK, TPB>>>(x, out, w1, b1, w2, b2);
}

// round 6
// speedup vs baseline: 1.1656x; 1.1656x over previous
#include <cuda_runtime.h>
#include <cuda_bf16.h>

// CALayer SE, single-pass persistent kernel, software-pipelined.
// 1024 co-resident blocks (launch_bounds(256,7): 7x148=1036 slots), each owns
// a quarter-plane (16KB) of one channel. Pipeline over 16 batches:
//   round b: read+sum batch b (fills L2), publish; then wait(b-1) [~free],
//            MLP(b-1), re-read batch b-1 from L2, scale, st.cs out.
// DRAM read stream is continuous; barrier latency hidden by the next read.
// Traffic: x read once + out written once = 537MB.

#define BATCH 16
#define CHAN 256
#define CR 16
#define HW 16384               // floats per plane
#define PLANE_F4 (HW/4)        // 4096
#define QF4 (PLANE_F4/4)       // 1024 float4 per quarter chunk
#define NBLK 1024
#define TPB 256

__device__ float g_part[BATCH * CHAN * 4];
__device__ int   g_cnt[BATCH];

__global__ void init_kernel() {
    if (threadIdx.x < BATCH) g_cnt[threadIdx.x] = 0;
}

__device__ __forceinline__ void stcs4(float4* p, float4 v) {
    asm volatile("st.global.cs.v4.f32 [%0], {%1,%2,%3,%4};"
                 :: "l"(p), "f"(v.x), "f"(v.y), "f"(v.z), "f"(v.w) : "memory");
}

__global__ __launch_bounds__(TPB, 7) void fused_se_kernel(
    const float* __restrict__ x, float* __restrict__ out,
    const float* __restrict__ w1, const float* __restrict__ b1,
    const float* __restrict__ w2, const float* __restrict__ b2)
{
    __shared__ float sred[8];
    __shared__ float smean[CHAN];
    __shared__ float shid[CR];
    __shared__ float sscale;

    const int chan    = blockIdx.x >> 2;   // 0..255
    const int quarter = blockIdx.x & 3;    // 0..3
    const int tid  = threadIdx.x;
    const int lane = tid & 31;
    const int wid  = tid >> 5;
    const size_t qoff = (size_t)quarter * QF4;

    const float4* __restrict__ x4 = reinterpret_cast<const float4*>(x);
    float4* __restrict__ o4 = reinterpret_cast<float4*>(out);

    // ---------- helpers inlined via lambdas ----------
    auto read_sum = [&](int b) {
        const int p = (b << 8) | chan;
        const float4* __restrict__ xp = x4 + (size_t)p * PLANE_F4 + qoff;
        float acc = 0.f;
        #pragma unroll
        for (int i = 0; i < 4; i++) {
            float4 v = xp[tid + i * TPB];          // .ca -> L2 resident
            acc += (v.x + v.y) + (v.z + v.w);
        }
        #pragma unroll
        for (int o = 16; o; o >>= 1) acc += __shfl_xor_sync(0xFFFFFFFF, acc, o);
        if (lane == 0) sred[wid] = acc;
        __syncthreads();
        if (tid == 0) {
            float t = 0.f;
            #pragma unroll
            for (int w = 0; w < 8; w++) t += sred[w];
            g_part[p * 4 + quarter] = t;
            __threadfence();
            atomicAdd(&g_cnt[b], 1);
        }
        __syncthreads();   // sred reusable next round
    };

    auto gate_scale = [&](int b) {
        // wait until all 1024 blocks published batch b (usually instant)
        if (tid == 0) {
            while (atomicAdd(&g_cnt[b], 0) < NBLK) __nanosleep(64);
            __threadfence();
        }
        __syncthreads();
        // means: tid == channel index
        {
            const int q = ((b << 8) + tid) * 4;
            smean[tid] = (__ldcg(&g_part[q]) + __ldcg(&g_part[q + 1]) +
                          __ldcg(&g_part[q + 2]) + __ldcg(&g_part[q + 3])) * (1.0f / HW);
        }
        __syncthreads();
        // hidden layer: 8 warps x 2 rows
        #pragma unroll
        for (int k = 0; k < 2; k++) {
            const int r = wid * 2 + k;
            float acc = 0.f;
            #pragma unroll
            for (int c = lane; c < CHAN; c += 32)
                acc += __ldg(&w1[r * CHAN + c]) * smean[c];
            #pragma unroll
            for (int o = 16; o; o >>= 1) acc += __shfl_xor_sync(0xFFFFFFFF, acc, o);
            if (lane == 0) shid[r] = fmaxf(acc + __ldg(&b1[r]), 0.f);
        }
        __syncthreads();
        if (tid == 0) {
            float acc = __ldg(&b2[chan]);
            #pragma unroll
            for (int r = 0; r < CR; r++)
                acc += __ldg(&w2[chan * CR + r]) * shid[r];
            sscale = 1.0f / (1.0f + __expf(-acc));
        }
        __syncthreads();
        // re-read from L2, scale, stream out
        const float sc = sscale;
        const int p = (b << 8) | chan;
        const float4* __restrict__ xp = x4 + (size_t)p * PLANE_F4 + qoff;
        float4* __restrict__ op = o4 + (size_t)p * PLANE_F4 + qoff;
        #pragma unroll
        for (int i = 0; i < 4; i++) {
            float4 v = xp[tid + i * TPB];          // L2 hit
            v.x *= sc; v.y *= sc; v.z *= sc; v.w *= sc;
            stcs4(&op[tid + i * TPB], v);
        }
        __syncthreads();
    };

    // ---------- pipelined main loop ----------
    read_sum(0);
    for (int b = 1; b < BATCH; b++) {
        read_sum(b);        // keeps DRAM busy while (b-1) finishes publishing
        gate_scale(b - 1);
    }
    gate_scale(BATCH - 1);
}

extern "C" void kernel_launch(void* const* d_in, const int* in_sizes, int n_in,
                              void* d_out, int out_size) {
    const float* x  = (const float*)d_in[0];
    const float* w1 = (const float*)d_in[1];
    const float* b1 = (const float*)d_in[2];
    const float* w2 = (const float*)d_in[3];
    const float* b2 = (const float*)d_in[4];
    float* out = (float*)d_out;

    init_kernel<<<1, 32>>>();
    fused_se_kernel<<<NBLK, TPB>>>(x, out, w1, b1, w2, b2);
}